// round 2
// baseline (speedup 1.0000x reference)
#include <cuda_runtime.h>
#include <cuda_bf16.h>

// qpNet: z = max(-(x @ W^T + b), -1/EPS), EPS=1e-3  =>  z = -min(h, 1000)
// x: [B,5] f32, W: [5,5] f32, b: [5] f32, out: [B,5] f32. B = 4194304.
// Persistent grid-stride kernel: 4 CTAs/SM * 152 SMs, each thread loops over
// chunks of 4 rows (20 floats = 5 x float4). W/b loaded ONCE per thread.

#define NEG_CLAMP (-1000.0f)   // -1/EPS

__global__ __launch_bounds__(256, 4) void qp_kernel(
    const float* __restrict__ x,
    const float* __restrict__ W,
    const float* __restrict__ b,
    float* __restrict__ out,
    long long nchunks)
{
    // Load tiny W [5,5] and b [5] once per thread — amortized over ~7 chunks.
    float w[5][5], bb[5];
#pragma unroll
    for (int j = 0; j < 5; j++) {
        bb[j] = __ldg(b + j);
#pragma unroll
        for (int k = 0; k < 5; k++)
            w[j][k] = __ldg(W + j * 5 + k);
    }

    const long long stride = (long long)gridDim.x * blockDim.x;

    for (long long t = (long long)blockIdx.x * blockDim.x + threadIdx.x;
         t < nchunks; t += stride) {
        const long long base = t * 20;   // byte offset 80*t -> 16B aligned

        const float4* xin = reinterpret_cast<const float4*>(x + base);
        float4 v0 = xin[0];
        float4 v1 = xin[1];
        float4 v2 = xin[2];
        float4 v3 = xin[3];
        float4 v4 = xin[4];

        float xr[4][5];
        xr[0][0] = v0.x; xr[0][1] = v0.y; xr[0][2] = v0.z; xr[0][3] = v0.w; xr[0][4] = v1.x;
        xr[1][0] = v1.y; xr[1][1] = v1.z; xr[1][2] = v1.w; xr[1][3] = v2.x; xr[1][4] = v2.y;
        xr[2][0] = v2.z; xr[2][1] = v2.w; xr[2][2] = v3.x; xr[2][3] = v3.y; xr[2][4] = v3.z;
        xr[3][0] = v3.w; xr[3][1] = v4.x; xr[3][2] = v4.y; xr[3][3] = v4.z; xr[3][4] = v4.w;

        float zr[4][5];
#pragma unroll
        for (int r = 0; r < 4; r++) {
#pragma unroll
            for (int j = 0; j < 5; j++) {
                float h = bb[j];
#pragma unroll
                for (int k = 0; k < 5; k++)
                    h = fmaf(xr[r][k], w[j][k], h);
                zr[r][j] = fmaxf(-h, NEG_CLAMP);   // z = max(-h, -1000)
            }
        }

        float4* oout = reinterpret_cast<float4*>(out + base);
        oout[0] = make_float4(zr[0][0], zr[0][1], zr[0][2], zr[0][3]);
        oout[1] = make_float4(zr[0][4], zr[1][0], zr[1][1], zr[1][2]);
        oout[2] = make_float4(zr[1][3], zr[1][4], zr[2][0], zr[2][1]);
        oout[3] = make_float4(zr[2][2], zr[2][3], zr[2][4], zr[3][0]);
        oout[4] = make_float4(zr[3][1], zr[3][2], zr[3][3], zr[3][4]);
    }
}

extern "C" void kernel_launch(void* const* d_in, const int* in_sizes, int n_in,
                              void* d_out, int out_size)
{
    const float* x = (const float*)d_in[0];   // [B,5]
    const float* W = (const float*)d_in[1];   // [5,5]
    const float* b = (const float*)d_in[2];   // [5]
    float* out = (float*)d_out;               // [B,5]

    const long long B = in_sizes[0] / 5;          // 4194304
    const long long nchunks = B / 4;              // 1048576 (B divisible by 4)

    // Persistent: 4 CTAs/SM * 152 SMs on GB300.
    const int threads = 256;
    const int blocks = 152 * 4;                   // 608

    qp_kernel<<<blocks, threads>>>(x, W, b, out, nchunks);
}

// round 3
// speedup vs baseline: 1.3190x; 1.3190x over previous
#include <cuda_runtime.h>
#include <cuda_bf16.h>

// qpNet: z = max(-(x @ W^T + b), -1/EPS), EPS=1e-3  =>  z = max(-h, -1000)
// x: [B,5] f32, W: [5,5] f32, b: [5] f32, out: [B,5] f32. B = 4194304.
//
// R3: warp-coalesced global access via smem staging.
//   tile = 1024 rows = 5120 floats = 20 KB per block (256 threads, 4 rows/thread)
//   coalesced float4 LDG -> smem -> LDS.128 per-row (conflict-free: stride
//   20 words, gcd(20,32)=4 but 8-lane phases hit distinct banks) -> compute
//   -> STS back -> coalesced float4 STG.

#define NEG_CLAMP (-1000.0f)   // -1/EPS

__global__ __launch_bounds__(256) void qp_kernel(
    const float* __restrict__ x,
    const float* __restrict__ W,
    const float* __restrict__ b,
    float* __restrict__ out)
{
    __shared__ float4 tile[1280];   // 20 KB = 256 threads * 5 float4

    const int tid = threadIdx.x;
    const long long gbase4 = (long long)blockIdx.x * 1280;  // float4 index

    // ---- coalesced stage-in: 5 float4 per thread, lane-contiguous ----
    const float4* __restrict__ x4 = reinterpret_cast<const float4*>(x);
#pragma unroll
    for (int i = 0; i < 5; i++)
        tile[tid + 256 * i] = x4[gbase4 + tid + 256 * i];

    // ---- W [5,5] + b [5]: 9 vectorized loads (L1/L2 hits after 1st wave) ----
    float w[5][5], bb[5];
    {
        const float4* W4 = reinterpret_cast<const float4*>(W);
        float4 a0 = __ldg(W4 + 0);
        float4 a1 = __ldg(W4 + 1);
        float4 a2 = __ldg(W4 + 2);
        float4 a3 = __ldg(W4 + 3);
        float4 a4 = __ldg(W4 + 4);
        float4 a5 = __ldg(W4 + 5);
        float  a6 = __ldg(W + 24);
        w[0][0]=a0.x; w[0][1]=a0.y; w[0][2]=a0.z; w[0][3]=a0.w; w[0][4]=a1.x;
        w[1][0]=a1.y; w[1][1]=a1.z; w[1][2]=a1.w; w[1][3]=a2.x; w[1][4]=a2.y;
        w[2][0]=a2.z; w[2][1]=a2.w; w[2][2]=a3.x; w[2][3]=a3.y; w[2][4]=a3.z;
        w[3][0]=a3.w; w[3][1]=a4.x; w[3][2]=a4.y; w[3][3]=a4.z; w[3][4]=a4.w;
        w[4][0]=a5.x; w[4][1]=a5.y; w[4][2]=a5.z; w[4][3]=a5.w; w[4][4]=a6;
        const float4* b4 = reinterpret_cast<const float4*>(b);
        float4 bv = __ldg(b4);
        bb[0]=bv.x; bb[1]=bv.y; bb[2]=bv.z; bb[3]=bv.w; bb[4]=__ldg(b + 4);
    }

    __syncthreads();

    // ---- read own 4 rows (20 floats) via 5x LDS.128, conflict-free ----
    float4 v[5];
#pragma unroll
    for (int i = 0; i < 5; i++)
        v[i] = tile[5 * tid + i];

    float xr[4][5];
    xr[0][0]=v[0].x; xr[0][1]=v[0].y; xr[0][2]=v[0].z; xr[0][3]=v[0].w; xr[0][4]=v[1].x;
    xr[1][0]=v[1].y; xr[1][1]=v[1].z; xr[1][2]=v[1].w; xr[1][3]=v[2].x; xr[1][4]=v[2].y;
    xr[2][0]=v[2].z; xr[2][1]=v[2].w; xr[2][2]=v[3].x; xr[2][3]=v[3].y; xr[2][4]=v[3].z;
    xr[3][0]=v[3].w; xr[3][1]=v[4].x; xr[3][2]=v[4].y; xr[3][3]=v[4].z; xr[3][4]=v[4].w;

    float zr[4][5];
#pragma unroll
    for (int r = 0; r < 4; r++) {
#pragma unroll
        for (int j = 0; j < 5; j++) {
            float h = bb[j];
#pragma unroll
            for (int k = 0; k < 5; k++)
                h = fmaf(xr[r][k], w[j][k], h);
            zr[r][j] = fmaxf(-h, NEG_CLAMP);
        }
    }

    __syncthreads();   // all reads of tile done before overwrite

    // ---- write results back to smem (conflict-free, same pattern) ----
    tile[5 * tid + 0] = make_float4(zr[0][0], zr[0][1], zr[0][2], zr[0][3]);
    tile[5 * tid + 1] = make_float4(zr[0][4], zr[1][0], zr[1][1], zr[1][2]);
    tile[5 * tid + 2] = make_float4(zr[1][3], zr[1][4], zr[2][0], zr[2][1]);
    tile[5 * tid + 3] = make_float4(zr[2][2], zr[2][3], zr[2][4], zr[3][0]);
    tile[5 * tid + 4] = make_float4(zr[3][1], zr[3][2], zr[3][3], zr[3][4]);

    __syncthreads();

    // ---- coalesced stage-out ----
    float4* __restrict__ o4 = reinterpret_cast<float4*>(out);
#pragma unroll
    for (int i = 0; i < 5; i++)
        o4[gbase4 + tid + 256 * i] = tile[tid + 256 * i];
}

extern "C" void kernel_launch(void* const* d_in, const int* in_sizes, int n_in,
                              void* d_out, int out_size)
{
    const float* x = (const float*)d_in[0];   // [B,5]
    const float* W = (const float*)d_in[1];   // [5,5]
    const float* b = (const float*)d_in[2];   // [5]
    float* out = (float*)d_out;               // [B,5]

    const long long B = in_sizes[0] / 5;      // 4194304
    const int threads = 256;
    // 1024 rows per block -> 4096 blocks, exact cover (B % 1024 == 0)
    const int blocks = (int)(B / 1024);

    qp_kernel<<<blocks, threads>>>(x, W, b, out);
}